// round 16
// baseline (speedup 1.0000x reference)
#include <cuda_runtime.h>
#include <cuda_bf16.h>
#include <cuda_fp16.h>
#include <cstdint>

typedef unsigned long long ull;

#define F128 128
#define NRBF 20
#define MAX_ATOMS 50000

// k_in / k_out fragment-ordered geometry (tf32 path)
#define S_STRIDE 72
#define NT_STRIDE (16 * S_STRIDE)    // 1152
#define SH_OUT (16 * NT_STRIDE)      // 18432 floats

// k_edge smem word offsets (32-bit words) — sW separate from H2, double-buffered sF2
#define EW_H2 0            // H2: fp16x2 [k2 0..63][stride 72] = 4608 words
#define EW_SW 4608         // sW: 64*132 fp32 = 8448 words
#define EW_F2 13056        // sF2: 2 x 1152 words (fp16x2 pairs, [kp][e] stride 72)
#define EW_RC 15360        // 2 x 64
#define EW_II 15488        // 2 x 64
#define EW_JJ 15616        // 2 x 64
#define EW_TOTAL 15744     // 62976 bytes

__device__ float g_h[(size_t)MAX_ATOMS * F128];
__device__ float g_agg[(size_t)MAX_ATOMS * F128];

// ---------- helpers ----------
__device__ __forceinline__ void red4(float* p, float4 v) {
    asm volatile("red.global.add.v4.f32 [%0], {%1,%2,%3,%4};" :: "l"(p), "f"(v.x), "f"(v.y), "f"(v.z), "f"(v.w) : "memory");
}
__device__ __forceinline__ float sspf(float x) {
    float e = __expf(-fabsf(x));
    return fmaxf(x, 0.0f) + __logf(1.0f + e) - 0.69314718056f;
}
__device__ __forceinline__ uint32_t tf32c(float f) {
    uint32_t u; asm("cvt.rna.tf32.f32 %0, %1;" : "=r"(u) : "f"(f)); return u;
}
__device__ __forceinline__ uint32_t packh2(float lo, float hi) {
    __half2 h = __floats2half2_rn(lo, hi);   // .x = lo
    return *reinterpret_cast<uint32_t*>(&h);
}
__device__ __forceinline__ void mma_tf32(float d[4], const uint32_t a[4], uint32_t b0, uint32_t b1) {
    asm volatile(
        "mma.sync.aligned.m16n8k8.row.col.f32.tf32.tf32.f32 "
        "{%0,%1,%2,%3}, {%4,%5,%6,%7}, {%8,%9}, {%0,%1,%2,%3};"
        : "+f"(d[0]), "+f"(d[1]), "+f"(d[2]), "+f"(d[3])
        : "r"(a[0]), "r"(a[1]), "r"(a[2]), "r"(a[3]), "r"(b0), "r"(b1));
}
__device__ __forceinline__ void mma_f16(float d[4], const uint32_t a[4], uint32_t b0, uint32_t b1) {
    asm volatile(
        "mma.sync.aligned.m16n8k16.row.col.f32.f16.f16.f32 "
        "{%0,%1,%2,%3}, {%4,%5,%6,%7}, {%8,%9}, {%0,%1,%2,%3};"
        : "+f"(d[0]), "+f"(d[1]), "+f"(d[2]), "+f"(d[3])
        : "r"(a[0]), "r"(a[1]), "r"(a[2]), "r"(a[3]), "r"(b0), "r"(b1));
}

// ---------- k_in: h = x @ W_in + b_in, plus zero g_agg ----------
__global__ void __launch_bounds__(512) k_in(const float* __restrict__ x,
                                            const float* __restrict__ W,
                                            const float* __restrict__ b, int nRows) {
    extern __shared__ float sm[];
    int t = threadIdx.x;
    int w = t >> 5, lane = t & 31;
    int lq = lane >> 2, lr = lane & 3;
    int fgrp = w & 7, ahalf = w >> 3;
    int fA = fgrp * 16 + lq;

    {
        size_t total4 = (size_t)nRows * 32;
        for (size_t i = (size_t)blockIdx.x * blockDim.x + t; i < total4;
             i += (size_t)gridDim.x * blockDim.x)
            ((float4*)g_agg)[i] = make_float4(0.f, 0.f, 0.f, 0.f);
    }

    uint32_t af[16][4];
#pragma unroll
    for (int s = 0; s < 16; s++) {
        af[s][0] = tf32c(__ldg(W + (8 * s + lr) * 128 + fA));
        af[s][1] = tf32c(__ldg(W + (8 * s + lr) * 128 + fA + 8));
        af[s][2] = tf32c(__ldg(W + (8 * s + 4 + lr) * 128 + fA));
        af[s][3] = tf32c(__ldg(W + (8 * s + 4 + lr) * 128 + fA + 8));
    }
    float b_lo = __ldg(b + fA), b_hi = __ldg(b + fA + 8);

    int nTiles = (nRows + 127) >> 7;
    for (int tile = blockIdx.x; tile < nTiles; tile += gridDim.x) {
        int r0 = tile << 7;
        __syncthreads();
        for (int idx = t; idx < 4096; idx += 512) {
            int atom = idx >> 5, kq = idx & 31;
            int row = r0 + atom;
            float4 v = (row < nRows) ? ((const float4*)(x + (size_t)row * 128))[kq]
                                     : make_float4(0.f, 0.f, 0.f, 0.f);
            int base = (atom >> 3) * NT_STRIDE + (kq >> 1) * S_STRIDE + 8 * (atom & 7) + (kq & 1);
            sm[base + 0] = __uint_as_float(tf32c(v.x));
            sm[base + 2] = __uint_as_float(tf32c(v.y));
            sm[base + 4] = __uint_as_float(tf32c(v.z));
            sm[base + 6] = __uint_as_float(tf32c(v.w));
        }
        __syncthreads();
        float acc[8][4];
#pragma unroll
        for (int nt = 0; nt < 8; nt++) {
            acc[nt][0] = b_lo; acc[nt][1] = b_lo;
            acc[nt][2] = b_hi; acc[nt][3] = b_hi;
        }
        const float2* bbase = (const float2*)sm + lane;
#pragma unroll
        for (int nt = 0; nt < 8; nt++) {
            int gnt = ahalf * 8 + nt;
            const float2* bp = bbase + gnt * (NT_STRIDE / 2);
#pragma unroll
            for (int s = 0; s < 16; s++) {
                float2 bb = bp[s * (S_STRIDE / 2)];
                mma_tf32(acc[nt], af[s], __float_as_uint(bb.x), __float_as_uint(bb.y));
            }
        }
#pragma unroll
        for (int nt = 0; nt < 8; nt++) {
            int gnt = ahalf * 8 + nt;
            int row0 = r0 + gnt * 8 + 2 * lr;
            if (row0 < nRows) {
                g_h[(size_t)row0 * 128 + fA] = acc[nt][0];
                g_h[(size_t)row0 * 128 + fA + 8] = acc[nt][2];
            }
            if (row0 + 1 < nRows) {
                g_h[(size_t)(row0 + 1) * 128 + fA] = acc[nt][1];
                g_h[(size_t)(row0 + 1) * 128 + fA + 8] = acc[nt][3];
            }
        }
    }
}

// ---------- fused edge pipeline: 3 barriers/tile + hoisted epilogue gathers ----------
__global__ void __launch_bounds__(256, 2) k_edge(const float* __restrict__ f_ij,
                                                 const float* __restrict__ rcut,
                                                 const int* __restrict__ idx_i,
                                                 const int* __restrict__ idx_j,
                                                 const float* __restrict__ Wf1,
                                                 const float* __restrict__ bf1,
                                                 const float* __restrict__ Wf2,
                                                 const float* __restrict__ bf2, int nPairs) {
    extern __shared__ float sm[];
    uint32_t* H2w = (uint32_t*)(sm + EW_H2);   // fp16x2 [k2][n], stride 72
    __half* Hh = (__half*)(sm + EW_H2);
    float* sW = sm + EW_SW;                    // fp32 64x132 (separate buffer)
    uint32_t* sF2 = (uint32_t*)(sm + EW_F2);   // 2 buffers of 1152
    float* sRc = sm + EW_RC;                   // 2 x 64
    int* sII = (int*)(sm + EW_II);             // 2 x 64
    int* sJJ = (int*)(sm + EW_JJ);             // 2 x 64

    int t = threadIdx.x;
    int w = t >> 5, lane = t & 31;
    int lq = lane >> 2, lr = lane & 3;

    // zero sF2 pads (kp 10..15) in BOTH buffers once
    for (int i = t; i < 864; i += 256) {
        int bsel = i / 432, o = i % 432;
        sF2[bsel * 1152 + 720 + o] = 0;
    }

    // per-lane bf2 (epilogue covers floats 4*lane..4*lane+3)
    float4 bf2v = ((const float4*)bf2)[lane];

    int fA = w * 16 + lq;
    // phase-2 A fragments
    uint32_t af[8][4];
#pragma unroll
    for (int s = 0; s < 8; s++) {
        int k0 = 16 * s + 2 * lr, k1 = 16 * s + 8 + 2 * lr;
        af[s][0] = packh2(Wf2[k0 * 128 + fA],     Wf2[(k0 + 1) * 128 + fA]);
        af[s][1] = packh2(Wf2[k0 * 128 + fA + 8], Wf2[(k0 + 1) * 128 + fA + 8]);
        af[s][2] = packh2(Wf2[k1 * 128 + fA],     Wf2[(k1 + 1) * 128 + fA]);
        af[s][3] = packh2(Wf2[k1 * 128 + fA + 8], Wf2[(k1 + 1) * 128 + fA + 8]);
    }
    // phase-1 A fragments
    uint32_t af1[2][4];
    {
        int k0 = 2 * lr, k1 = 8 + 2 * lr;
        af1[0][0] = packh2(Wf1[k0 * 128 + fA],     Wf1[(k0 + 1) * 128 + fA]);
        af1[0][1] = packh2(Wf1[k0 * 128 + fA + 8], Wf1[(k0 + 1) * 128 + fA + 8]);
        af1[0][2] = packh2(Wf1[k1 * 128 + fA],     Wf1[(k1 + 1) * 128 + fA]);
        af1[0][3] = packh2(Wf1[k1 * 128 + fA + 8], Wf1[(k1 + 1) * 128 + fA + 8]);
        int k2_ = 16 + 2 * lr;
        af1[1][0] = (k2_ < NRBF) ? packh2(Wf1[k2_ * 128 + fA],     Wf1[(k2_ + 1) * 128 + fA]) : 0u;
        af1[1][1] = (k2_ < NRBF) ? packh2(Wf1[k2_ * 128 + fA + 8], Wf1[(k2_ + 1) * 128 + fA + 8]) : 0u;
        af1[1][2] = 0u;
        af1[1][3] = 0u;
    }
    float blo = bf1[fA], bhi = bf1[fA + 8];
    int k2lo = fA >> 1;
    int par = fA & 1;

    // prefetch decomposition (4t never straddles a 20-float row)
    int eA = t / 5, kpA = ((4 * t) - eA * 20) >> 1;
    int gi2 = 1024 + 4 * (t & 63);
    int eB = gi2 / 20, kpB = (gi2 - eB * 20) >> 1;

    int nTiles = nPairs >> 6;
    int grid = gridDim.x;

    // first-tile prefetch
    float4 pfa = make_float4(0.f, 0.f, 0.f, 0.f), pfb = pfa;
    float prc = 0.f; int pii = 0, pjj = 0;
    if (blockIdx.x < nTiles) {
        size_t e0g = (size_t)blockIdx.x << 6;
        pfa = *(const float4*)(f_ij + e0g * NRBF + 4 * t);
        if (t < 64) {
            pfb = *(const float4*)(f_ij + e0g * NRBF + gi2);
            prc = rcut[e0g + t];
            pii = idx_i[e0g + t];
            pjj = idx_j[e0g + t];
        }
    }

    int buf = 0;
    for (int tile = blockIdx.x; tile < nTiles; tile += grid, buf ^= 1) {
        uint32_t* F2b = sF2 + buf * 1152;
        float* Rcb = sRc + buf * 64;
        int* IIb = sII + buf * 64;
        int* JJb = sJJ + buf * 64;
        // store prefetched edge data into this tile's buffer
        F2b[kpA * 72 + eA]       = packh2(pfa.x, pfa.y);
        F2b[(kpA + 1) * 72 + eA] = packh2(pfa.z, pfa.w);
        if (t < 64) {
            F2b[kpB * 72 + eB]       = packh2(pfb.x, pfb.y);
            F2b[(kpB + 1) * 72 + eB] = packh2(pfb.z, pfb.w);
            Rcb[t] = prc;
            IIb[t] = pii;
            JJb[t] = pjj;
        }
        __syncthreads();  // sync1: F2b stores visible; prev tile epilogue fully done
        // ---- phase 1: hidden = ssp(f @ Wf1 + bf1), fp16 mma -> H2 ----
#pragma unroll
        for (int nt = 0; nt < 8; nt++) {
            float a4[4] = {0.f, 0.f, 0.f, 0.f};
            int n = 8 * nt + lq;
            uint32_t b00 = F2b[lr * 72 + n];
            uint32_t b01 = F2b[(4 + lr) * 72 + n];
            mma_f16(a4, af1[0], b00, b01);
            uint32_t b10 = F2b[(8 + lr) * 72 + n];
            uint32_t b11 = F2b[(12 + lr) * 72 + n];
            mma_f16(a4, af1[1], b10, b11);
            int e0 = nt * 8 + 2 * lr;
            Hh[(k2lo * 72 + e0) * 2 + par]           = __float2half_rn(sspf(a4[0] + blo));
            Hh[(k2lo * 72 + e0 + 1) * 2 + par]       = __float2half_rn(sspf(a4[1] + blo));
            Hh[((k2lo + 4) * 72 + e0) * 2 + par]     = __float2half_rn(sspf(a4[2] + bhi));
            Hh[((k2lo + 4) * 72 + e0 + 1) * 2 + par] = __float2half_rn(sspf(a4[3] + bhi));
        }
        __syncthreads();  // sync2: H2 visible
        // ---- phase 2: Wij = hidden @ Wf2 ----
        float acc[8][4];
#pragma unroll
        for (int nt = 0; nt < 8; nt++)
#pragma unroll
            for (int c = 0; c < 4; c++) acc[nt][c] = 0.0f;
#pragma unroll
        for (int s = 0; s < 8; s++) {
            int rb0 = (8 * s + lr) * 72 + lq;
            int rb1 = rb0 + 288;
#pragma unroll
            for (int nt = 0; nt < 8; nt++) {
                uint32_t b0 = H2w[rb0 + 8 * nt];
                uint32_t b1 = H2w[rb1 + 8 * nt];
                mma_f16(acc[nt], af[s], b0, b1);
            }
        }
        // ---- writeback fragments -> sW (separate buffer; prev epilogue done at sync1) ----
#pragma unroll
        for (int nt = 0; nt < 8; nt++) {
            int eb = nt * 8 + 2 * lr;
            sW[eb * 132 + fA]           = acc[nt][0];
            sW[(eb + 1) * 132 + fA]     = acc[nt][1];
            sW[eb * 132 + fA + 8]       = acc[nt][2];
            sW[(eb + 1) * 132 + fA + 8] = acc[nt][3];
        }
        // ---- hoisted epilogue gathers (first 4 edges): indices stable since sync1,
        //      g_h read-only — overlap L2 latency with prefetch + sync3 drain ----
        int ew0 = w * 8;
        float rcb0[4]; int iib0[4]; float4 hv0[4];
#pragma unroll
        for (int k = 0; k < 4; k++) {
            int e = ew0 + k;
            rcb0[k] = Rcb[e];
            iib0[k] = IIb[e];
            hv0[k] = ((const float4*)(g_h + (size_t)JJb[e] * 128))[lane];
        }
        // ---- issue NEXT tile's prefetch (overlaps epilogue + barrier) ----
        {
            int ntile = tile + grid;
            if (ntile < nTiles) {
                size_t e0g = (size_t)ntile << 6;
                pfa = *(const float4*)(f_ij + e0g * NRBF + 4 * t);
                if (t < 64) {
                    pfb = *(const float4*)(f_ij + e0g * NRBF + gi2);
                    prc = rcut[e0g + t];
                    pii = idx_i[e0g + t];
                    pjj = idx_j[e0g + t];
                }
            }
        }
        __syncthreads();  // sync3: sW visible; all H2 reads done
        // ---- epilogue ----
        {
            // first half: hv already in registers
#pragma unroll
            for (int k = 0; k < 4; k++) {
                int e = ew0 + k;
                float4 wv = *(const float4*)(sW + e * 132 + 4 * lane);
                red4(g_agg + (size_t)iib0[k] * 128 + 4 * lane,
                     make_float4((wv.x + bf2v.x) * rcb0[k] * hv0[k].x,
                                 (wv.y + bf2v.y) * rcb0[k] * hv0[k].y,
                                 (wv.z + bf2v.z) * rcb0[k] * hv0[k].z,
                                 (wv.w + bf2v.w) * rcb0[k] * hv0[k].w));
            }
            // second half: batched gather then RED
            float rcb[4]; int iib[4];
            float4 hv[4], wv[4];
#pragma unroll
            for (int k = 0; k < 4; k++) {
                int e = ew0 + 4 + k;
                rcb[k] = Rcb[e];
                int jj = JJb[e];
                iib[k] = IIb[e];
                hv[k] = ((const float4*)(g_h + (size_t)jj * 128))[lane];
                wv[k] = *(const float4*)(sW + e * 132 + 4 * lane);
            }
#pragma unroll
            for (int k = 0; k < 4; k++) {
                red4(g_agg + (size_t)iib[k] * 128 + 4 * lane,
                     make_float4((wv[k].x + bf2v.x) * rcb[k] * hv[k].x,
                                 (wv[k].y + bf2v.y) * rcb[k] * hv[k].y,
                                 (wv[k].z + bf2v.z) * rcb[k] * hv[k].z,
                                 (wv[k].w + bf2v.w) * rcb[k] * hv[k].w));
            }
        }
    }
}

// ---------- k_out: out = ssp(agg@Wo1+bo1)@Wo2+bo2 (tf32 mma) ----------
__global__ void __launch_bounds__(512) k_out(const float* __restrict__ Wo1,
                                             const float* __restrict__ bo1,
                                             const float* __restrict__ Wo2,
                                             const float* __restrict__ bo2,
                                             float* __restrict__ out, int nRows) {
    extern __shared__ float sm[];
    int t = threadIdx.x;
    int w = t >> 5, lane = t & 31;
    int lq = lane >> 2, lr = lane & 3;
    int fgrp = w & 7, ahalf = w >> 3;
    int fA = fgrp * 16 + lq;

    int p2_lo = (2 * fgrp) * S_STRIDE + 2 * (lq & 3) + (lq >> 2);
    int p2_hi = p2_lo + S_STRIDE;

    float bo1_lo = __ldg(bo1 + fA), bo1_hi = __ldg(bo1 + fA + 8);
    float bo2_lo = __ldg(bo2 + fA), bo2_hi = __ldg(bo2 + fA + 8);

    const float2* bbase = (const float2*)sm + lane;

    int nTiles = (nRows + 127) >> 7;
    for (int tile = blockIdx.x; tile < nTiles; tile += gridDim.x) {
        int r0 = tile << 7;
        __syncthreads();
        for (int idx = t; idx < 4096; idx += 512) {
            int atom = idx >> 5, kq = idx & 31;
            int row = r0 + atom;
            float4 v = (row < nRows) ? ((const float4*)(g_agg + (size_t)row * 128))[kq]
                                     : make_float4(0.f, 0.f, 0.f, 0.f);
            int base = (atom >> 3) * NT_STRIDE + (kq >> 1) * S_STRIDE + 8 * (atom & 7) + (kq & 1);
            sm[base + 0] = __uint_as_float(tf32c(v.x));
            sm[base + 2] = __uint_as_float(tf32c(v.y));
            sm[base + 4] = __uint_as_float(tf32c(v.z));
            sm[base + 6] = __uint_as_float(tf32c(v.w));
        }
        uint32_t af[16][4];
#pragma unroll
        for (int s = 0; s < 16; s++) {
            af[s][0] = tf32c(__ldg(Wo1 + (8 * s + lr) * 128 + fA));
            af[s][1] = tf32c(__ldg(Wo1 + (8 * s + lr) * 128 + fA + 8));
            af[s][2] = tf32c(__ldg(Wo1 + (8 * s + 4 + lr) * 128 + fA));
            af[s][3] = tf32c(__ldg(Wo1 + (8 * s + 4 + lr) * 128 + fA + 8));
        }
        __syncthreads();
        float acc[8][4];
#pragma unroll
        for (int nt = 0; nt < 8; nt++) {
            acc[nt][0] = bo1_lo; acc[nt][1] = bo1_lo;
            acc[nt][2] = bo1_hi; acc[nt][3] = bo1_hi;
        }
#pragma unroll
        for (int nt = 0; nt < 8; nt++) {
            int gnt = ahalf * 8 + nt;
            const float2* bp = bbase + gnt * (NT_STRIDE / 2);
#pragma unroll
            for (int s = 0; s < 16; s++) {
                float2 bb = bp[s * (S_STRIDE / 2)];
                mma_tf32(acc[nt], af[s], __float_as_uint(bb.x), __float_as_uint(bb.y));
            }
        }
        __syncthreads();
#pragma unroll
        for (int nt = 0; nt < 8; nt++) {
            int gnt = ahalf * 8 + nt;
            float* base = sm + gnt * NT_STRIDE;
            int e0 = 2 * lr;
            base[p2_lo + e0 * 8]       = __uint_as_float(tf32c(sspf(acc[nt][0])));
            base[p2_lo + (e0 + 1) * 8] = __uint_as_float(tf32c(sspf(acc[nt][1])));
            base[p2_hi + e0 * 8]       = __uint_as_float(tf32c(sspf(acc[nt][2])));
            base[p2_hi + (e0 + 1) * 8] = __uint_as_float(tf32c(sspf(acc[nt][3])));
        }
#pragma unroll
        for (int s = 0; s < 16; s++) {
            af[s][0] = tf32c(__ldg(Wo2 + (8 * s + lr) * 128 + fA));
            af[s][1] = tf32c(__ldg(Wo2 + (8 * s + lr) * 128 + fA + 8));
            af[s][2] = tf32c(__ldg(Wo2 + (8 * s + 4 + lr) * 128 + fA));
            af[s][3] = tf32c(__ldg(Wo2 + (8 * s + 4 + lr) * 128 + fA + 8));
        }
        __syncthreads();
#pragma unroll
        for (int nt = 0; nt < 8; nt++) {
            acc[nt][0] = bo2_lo; acc[nt][1] = bo2_lo;
            acc[nt][2] = bo2_hi; acc[nt][3] = bo2_hi;
        }
#pragma unroll
        for (int nt = 0; nt < 8; nt++) {
            int gnt = ahalf * 8 + nt;
            const float2* bp = bbase + gnt * (NT_STRIDE / 2);
#pragma unroll
            for (int s = 0; s < 16; s++) {
                float2 bb = bp[s * (S_STRIDE / 2)];
                mma_tf32(acc[nt], af[s], __float_as_uint(bb.x), __float_as_uint(bb.y));
            }
        }
#pragma unroll
        for (int nt = 0; nt < 8; nt++) {
            int gnt = ahalf * 8 + nt;
            int row0 = r0 + gnt * 8 + 2 * lr;
            if (row0 < nRows) {
                out[(size_t)row0 * 128 + fA] = acc[nt][0];
                out[(size_t)row0 * 128 + fA + 8] = acc[nt][2];
            }
            if (row0 + 1 < nRows) {
                out[(size_t)(row0 + 1) * 128 + fA] = acc[nt][1];
                out[(size_t)(row0 + 1) * 128 + fA + 8] = acc[nt][3];
            }
        }
    }
}

// ---------- launch ----------
extern "C" void kernel_launch(void* const* d_in, const int* in_sizes, int n_in,
                              void* d_out, int out_size) {
    const float* x    = (const float*)d_in[0];
    const float* f_ij = (const float*)d_in[1];
    const float* rcut = (const float*)d_in[2];
    const float* W_in = (const float*)d_in[3];
    const float* b_in = (const float*)d_in[4];
    const float* Wf1  = (const float*)d_in[5];
    const float* bf1  = (const float*)d_in[6];
    const float* Wf2  = (const float*)d_in[7];
    const float* bf2  = (const float*)d_in[8];
    const float* Wo1  = (const float*)d_in[9];
    const float* bo1  = (const float*)d_in[10];
    const float* Wo2  = (const float*)d_in[11];
    const float* bo2  = (const float*)d_in[12];
    const int* idx_i  = (const int*)d_in[13];
    const int* idx_j  = (const int*)d_in[14];
    float* out = (float*)d_out;

    int nAtoms = in_sizes[0] / 128;
    int nPairs = in_sizes[2];

    const int SMEM_INOUT = SH_OUT * 4;       // 73728
    const int SMEM_EDGE  = EW_TOTAL * 4;     // 62976

    cudaFuncSetAttribute(k_in, cudaFuncAttributeMaxDynamicSharedMemorySize, SMEM_INOUT);
    cudaFuncSetAttribute(k_edge, cudaFuncAttributeMaxDynamicSharedMemorySize, SMEM_EDGE);
    cudaFuncSetAttribute(k_out, cudaFuncAttributeMaxDynamicSharedMemorySize, SMEM_INOUT);

    int rowTiles = (nAtoms + 127) / 128;
    k_in<<<rowTiles, 512, SMEM_INOUT>>>(x, W_in, b_in, nAtoms);
    k_edge<<<296, 256, SMEM_EDGE>>>(f_ij, rcut, idx_i, idx_j, Wf1, bf1, Wf2, bf2, nPairs);
    k_out<<<rowTiles, 512, SMEM_INOUT>>>(Wo1, bo1, Wo2, bo2, out, nAtoms);
}

// round 17
// speedup vs baseline: 1.5739x; 1.5739x over previous
#include <cuda_runtime.h>
#include <cuda_bf16.h>
#include <cuda_fp16.h>
#include <cstdint>

typedef unsigned long long ull;

#define F128 128
#define NRBF 20
#define MAX_ATOMS 50000

// k_in / k_out fragment-ordered geometry (tf32 path)
#define S_STRIDE 72
#define NT_STRIDE (16 * S_STRIDE)    // 1152
#define SH_OUT (16 * NT_STRIDE)      // 18432 floats

// k_edge smem word offsets (32-bit words) — sW separate from H2, double-buffered sF2
#define EW_H2 0            // H2: fp16x2 [k2 0..63][stride 72] = 4608 words
#define EW_SW 4608         // sW: 64*132 fp32 = 8448 words
#define EW_F2 13056        // sF2: 2 x 1152 words (fp16x2 pairs, [kp][e] stride 72)
#define EW_RC 15360        // 2 x 64
#define EW_II 15488        // 2 x 64
#define EW_JJ 15616        // 2 x 64
#define EW_TOTAL 15744     // 62976 bytes

__device__ float g_h[(size_t)MAX_ATOMS * F128];
__device__ float g_agg[(size_t)MAX_ATOMS * F128];

// ---------- helpers ----------
__device__ __forceinline__ void red4(float* p, float4 v) {
    asm volatile("red.global.add.v4.f32 [%0], {%1,%2,%3,%4};" :: "l"(p), "f"(v.x), "f"(v.y), "f"(v.z), "f"(v.w) : "memory");
}
__device__ __forceinline__ float sspf(float x) {
    float e = __expf(-fabsf(x));
    return fmaxf(x, 0.0f) + __logf(1.0f + e) - 0.69314718056f;
}
__device__ __forceinline__ uint32_t tf32c(float f) {
    uint32_t u; asm("cvt.rna.tf32.f32 %0, %1;" : "=r"(u) : "f"(f)); return u;
}
__device__ __forceinline__ uint32_t packh2(float lo, float hi) {
    __half2 h = __floats2half2_rn(lo, hi);   // .x = lo
    return *reinterpret_cast<uint32_t*>(&h);
}
__device__ __forceinline__ void mma_tf32(float d[4], const uint32_t a[4], uint32_t b0, uint32_t b1) {
    asm volatile(
        "mma.sync.aligned.m16n8k8.row.col.f32.tf32.tf32.f32 "
        "{%0,%1,%2,%3}, {%4,%5,%6,%7}, {%8,%9}, {%0,%1,%2,%3};"
        : "+f"(d[0]), "+f"(d[1]), "+f"(d[2]), "+f"(d[3])
        : "r"(a[0]), "r"(a[1]), "r"(a[2]), "r"(a[3]), "r"(b0), "r"(b1));
}
__device__ __forceinline__ void mma_f16(float d[4], const uint32_t a[4], uint32_t b0, uint32_t b1) {
    asm volatile(
        "mma.sync.aligned.m16n8k16.row.col.f32.f16.f16.f32 "
        "{%0,%1,%2,%3}, {%4,%5,%6,%7}, {%8,%9}, {%0,%1,%2,%3};"
        : "+f"(d[0]), "+f"(d[1]), "+f"(d[2]), "+f"(d[3])
        : "r"(a[0]), "r"(a[1]), "r"(a[2]), "r"(a[3]), "r"(b0), "r"(b1));
}

// ---------- k_in: h = x @ W_in + b_in, plus zero g_agg ----------
__global__ void __launch_bounds__(512) k_in(const float* __restrict__ x,
                                            const float* __restrict__ W,
                                            const float* __restrict__ b, int nRows) {
    extern __shared__ float sm[];
    int t = threadIdx.x;
    int w = t >> 5, lane = t & 31;
    int lq = lane >> 2, lr = lane & 3;
    int fgrp = w & 7, ahalf = w >> 3;
    int fA = fgrp * 16 + lq;

    {
        size_t total4 = (size_t)nRows * 32;
        for (size_t i = (size_t)blockIdx.x * blockDim.x + t; i < total4;
             i += (size_t)gridDim.x * blockDim.x)
            ((float4*)g_agg)[i] = make_float4(0.f, 0.f, 0.f, 0.f);
    }

    uint32_t af[16][4];
#pragma unroll
    for (int s = 0; s < 16; s++) {
        af[s][0] = tf32c(__ldg(W + (8 * s + lr) * 128 + fA));
        af[s][1] = tf32c(__ldg(W + (8 * s + lr) * 128 + fA + 8));
        af[s][2] = tf32c(__ldg(W + (8 * s + 4 + lr) * 128 + fA));
        af[s][3] = tf32c(__ldg(W + (8 * s + 4 + lr) * 128 + fA + 8));
    }
    float b_lo = __ldg(b + fA), b_hi = __ldg(b + fA + 8);

    int nTiles = (nRows + 127) >> 7;
    for (int tile = blockIdx.x; tile < nTiles; tile += gridDim.x) {
        int r0 = tile << 7;
        __syncthreads();
        for (int idx = t; idx < 4096; idx += 512) {
            int atom = idx >> 5, kq = idx & 31;
            int row = r0 + atom;
            float4 v = (row < nRows) ? ((const float4*)(x + (size_t)row * 128))[kq]
                                     : make_float4(0.f, 0.f, 0.f, 0.f);
            int base = (atom >> 3) * NT_STRIDE + (kq >> 1) * S_STRIDE + 8 * (atom & 7) + (kq & 1);
            sm[base + 0] = __uint_as_float(tf32c(v.x));
            sm[base + 2] = __uint_as_float(tf32c(v.y));
            sm[base + 4] = __uint_as_float(tf32c(v.z));
            sm[base + 6] = __uint_as_float(tf32c(v.w));
        }
        __syncthreads();
        float acc[8][4];
#pragma unroll
        for (int nt = 0; nt < 8; nt++) {
            acc[nt][0] = b_lo; acc[nt][1] = b_lo;
            acc[nt][2] = b_hi; acc[nt][3] = b_hi;
        }
        const float2* bbase = (const float2*)sm + lane;
#pragma unroll
        for (int nt = 0; nt < 8; nt++) {
            int gnt = ahalf * 8 + nt;
            const float2* bp = bbase + gnt * (NT_STRIDE / 2);
#pragma unroll
            for (int s = 0; s < 16; s++) {
                float2 bb = bp[s * (S_STRIDE / 2)];
                mma_tf32(acc[nt], af[s], __float_as_uint(bb.x), __float_as_uint(bb.y));
            }
        }
#pragma unroll
        for (int nt = 0; nt < 8; nt++) {
            int gnt = ahalf * 8 + nt;
            int row0 = r0 + gnt * 8 + 2 * lr;
            if (row0 < nRows) {
                g_h[(size_t)row0 * 128 + fA] = acc[nt][0];
                g_h[(size_t)row0 * 128 + fA + 8] = acc[nt][2];
            }
            if (row0 + 1 < nRows) {
                g_h[(size_t)(row0 + 1) * 128 + fA] = acc[nt][1];
                g_h[(size_t)(row0 + 1) * 128 + fA + 8] = acc[nt][3];
            }
        }
    }
}

// ---------- fused edge pipeline: 3 barriers/tile + hoisted epilogue gathers ----------
__global__ void __launch_bounds__(256, 2) k_edge(const float* __restrict__ f_ij,
                                                 const float* __restrict__ rcut,
                                                 const int* __restrict__ idx_i,
                                                 const int* __restrict__ idx_j,
                                                 const float* __restrict__ Wf1,
                                                 const float* __restrict__ bf1,
                                                 const float* __restrict__ Wf2,
                                                 const float* __restrict__ bf2, int nPairs) {
    extern __shared__ float sm[];
    uint32_t* H2w = (uint32_t*)(sm + EW_H2);   // fp16x2 [k2][n], stride 72
    __half* Hh = (__half*)(sm + EW_H2);
    float* sW = sm + EW_SW;                    // fp32 64x132 (separate buffer)
    uint32_t* sF2 = (uint32_t*)(sm + EW_F2);   // 2 buffers of 1152
    float* sRc = sm + EW_RC;                   // 2 x 64
    int* sII = (int*)(sm + EW_II);             // 2 x 64
    int* sJJ = (int*)(sm + EW_JJ);             // 2 x 64

    int t = threadIdx.x;
    int w = t >> 5, lane = t & 31;
    int lq = lane >> 2, lr = lane & 3;

    // zero sF2 pads (kp 10..15) in BOTH buffers once
    for (int i = t; i < 864; i += 256) {
        int bsel = i / 432, o = i % 432;
        sF2[bsel * 1152 + 720 + o] = 0;
    }

    // per-lane bf2 (epilogue covers floats 4*lane..4*lane+3)
    float4 bf2v = ((const float4*)bf2)[lane];

    int fA = w * 16 + lq;
    // phase-2 A fragments
    uint32_t af[8][4];
#pragma unroll
    for (int s = 0; s < 8; s++) {
        int k0 = 16 * s + 2 * lr, k1 = 16 * s + 8 + 2 * lr;
        af[s][0] = packh2(Wf2[k0 * 128 + fA],     Wf2[(k0 + 1) * 128 + fA]);
        af[s][1] = packh2(Wf2[k0 * 128 + fA + 8], Wf2[(k0 + 1) * 128 + fA + 8]);
        af[s][2] = packh2(Wf2[k1 * 128 + fA],     Wf2[(k1 + 1) * 128 + fA]);
        af[s][3] = packh2(Wf2[k1 * 128 + fA + 8], Wf2[(k1 + 1) * 128 + fA + 8]);
    }
    // phase-1 A fragments
    uint32_t af1[2][4];
    {
        int k0 = 2 * lr, k1 = 8 + 2 * lr;
        af1[0][0] = packh2(Wf1[k0 * 128 + fA],     Wf1[(k0 + 1) * 128 + fA]);
        af1[0][1] = packh2(Wf1[k0 * 128 + fA + 8], Wf1[(k0 + 1) * 128 + fA + 8]);
        af1[0][2] = packh2(Wf1[k1 * 128 + fA],     Wf1[(k1 + 1) * 128 + fA]);
        af1[0][3] = packh2(Wf1[k1 * 128 + fA + 8], Wf1[(k1 + 1) * 128 + fA + 8]);
        int k2_ = 16 + 2 * lr;
        af1[1][0] = (k2_ < NRBF) ? packh2(Wf1[k2_ * 128 + fA],     Wf1[(k2_ + 1) * 128 + fA]) : 0u;
        af1[1][1] = (k2_ < NRBF) ? packh2(Wf1[k2_ * 128 + fA + 8], Wf1[(k2_ + 1) * 128 + fA + 8]) : 0u;
        af1[1][2] = 0u;
        af1[1][3] = 0u;
    }
    float blo = bf1[fA], bhi = bf1[fA + 8];
    int k2lo = fA >> 1;
    int par = fA & 1;

    // prefetch decomposition (4t never straddles a 20-float row)
    int eA = t / 5, kpA = ((4 * t) - eA * 20) >> 1;
    int gi2 = 1024 + 4 * (t & 63);
    int eB = gi2 / 20, kpB = (gi2 - eB * 20) >> 1;

    int nTiles = nPairs >> 6;
    int grid = gridDim.x;

    // first-tile prefetch
    float4 pfa = make_float4(0.f, 0.f, 0.f, 0.f), pfb = pfa;
    float prc = 0.f; int pii = 0, pjj = 0;
    if (blockIdx.x < nTiles) {
        size_t e0g = (size_t)blockIdx.x << 6;
        pfa = *(const float4*)(f_ij + e0g * NRBF + 4 * t);
        if (t < 64) {
            pfb = *(const float4*)(f_ij + e0g * NRBF + gi2);
            prc = rcut[e0g + t];
            pii = idx_i[e0g + t];
            pjj = idx_j[e0g + t];
        }
    }

    int buf = 0;
    for (int tile = blockIdx.x; tile < nTiles; tile += grid, buf ^= 1) {
        uint32_t* F2b = sF2 + buf * 1152;
        float* Rcb = sRc + buf * 64;
        int* IIb = sII + buf * 64;
        int* JJb = sJJ + buf * 64;
        // store prefetched edge data into this tile's buffer
        F2b[kpA * 72 + eA]       = packh2(pfa.x, pfa.y);
        F2b[(kpA + 1) * 72 + eA] = packh2(pfa.z, pfa.w);
        if (t < 64) {
            F2b[kpB * 72 + eB]       = packh2(pfb.x, pfb.y);
            F2b[(kpB + 1) * 72 + eB] = packh2(pfb.z, pfb.w);
            Rcb[t] = prc;
            IIb[t] = pii;
            JJb[t] = pjj;
        }
        __syncthreads();  // sync1: F2b stores visible; prev tile epilogue fully done
        // ---- phase 1: hidden = ssp(f @ Wf1 + bf1), fp16 mma -> H2 ----
#pragma unroll
        for (int nt = 0; nt < 8; nt++) {
            float a4[4] = {0.f, 0.f, 0.f, 0.f};
            int n = 8 * nt + lq;
            uint32_t b00 = F2b[lr * 72 + n];
            uint32_t b01 = F2b[(4 + lr) * 72 + n];
            mma_f16(a4, af1[0], b00, b01);
            uint32_t b10 = F2b[(8 + lr) * 72 + n];
            uint32_t b11 = F2b[(12 + lr) * 72 + n];
            mma_f16(a4, af1[1], b10, b11);
            int e0 = nt * 8 + 2 * lr;
            Hh[(k2lo * 72 + e0) * 2 + par]           = __float2half_rn(sspf(a4[0] + blo));
            Hh[(k2lo * 72 + e0 + 1) * 2 + par]       = __float2half_rn(sspf(a4[1] + blo));
            Hh[((k2lo + 4) * 72 + e0) * 2 + par]     = __float2half_rn(sspf(a4[2] + bhi));
            Hh[((k2lo + 4) * 72 + e0 + 1) * 2 + par] = __float2half_rn(sspf(a4[3] + bhi));
        }
        __syncthreads();  // sync2: H2 visible
        // ---- phase 2: Wij = hidden @ Wf2 ----
        float acc[8][4];
#pragma unroll
        for (int nt = 0; nt < 8; nt++)
#pragma unroll
            for (int c = 0; c < 4; c++) acc[nt][c] = 0.0f;
#pragma unroll
        for (int s = 0; s < 8; s++) {
            int rb0 = (8 * s + lr) * 72 + lq;
            int rb1 = rb0 + 288;
#pragma unroll
            for (int nt = 0; nt < 8; nt++) {
                uint32_t b0 = H2w[rb0 + 8 * nt];
                uint32_t b1 = H2w[rb1 + 8 * nt];
                mma_f16(acc[nt], af[s], b0, b1);
            }
        }
        // ---- writeback fragments -> sW (separate buffer; prev epilogue done at sync1) ----
#pragma unroll
        for (int nt = 0; nt < 8; nt++) {
            int eb = nt * 8 + 2 * lr;
            sW[eb * 132 + fA]           = acc[nt][0];
            sW[(eb + 1) * 132 + fA]     = acc[nt][1];
            sW[eb * 132 + fA + 8]       = acc[nt][2];
            sW[(eb + 1) * 132 + fA + 8] = acc[nt][3];
        }
        // ---- hoisted epilogue gathers (first 4 edges): indices stable since sync1,
        //      g_h read-only — overlap L2 latency with prefetch + sync3 drain ----
        int ew0 = w * 8;
        float rcb0[4]; int iib0[4]; float4 hv0[4];
#pragma unroll
        for (int k = 0; k < 4; k++) {
            int e = ew0 + k;
            rcb0[k] = Rcb[e];
            iib0[k] = IIb[e];
            hv0[k] = ((const float4*)(g_h + (size_t)JJb[e] * 128))[lane];
        }
        // ---- issue NEXT tile's prefetch (overlaps epilogue + barrier) ----
        {
            int ntile = tile + grid;
            if (ntile < nTiles) {
                size_t e0g = (size_t)ntile << 6;
                pfa = *(const float4*)(f_ij + e0g * NRBF + 4 * t);
                if (t < 64) {
                    pfb = *(const float4*)(f_ij + e0g * NRBF + gi2);
                    prc = rcut[e0g + t];
                    pii = idx_i[e0g + t];
                    pjj = idx_j[e0g + t];
                }
            }
        }
        __syncthreads();  // sync3: sW visible; all H2 reads done
        // ---- epilogue ----
        {
            // first half: hv already in registers
#pragma unroll
            for (int k = 0; k < 4; k++) {
                int e = ew0 + k;
                float4 wv = *(const float4*)(sW + e * 132 + 4 * lane);
                red4(g_agg + (size_t)iib0[k] * 128 + 4 * lane,
                     make_float4((wv.x + bf2v.x) * rcb0[k] * hv0[k].x,
                                 (wv.y + bf2v.y) * rcb0[k] * hv0[k].y,
                                 (wv.z + bf2v.z) * rcb0[k] * hv0[k].z,
                                 (wv.w + bf2v.w) * rcb0[k] * hv0[k].w));
            }
            // second half: batched gather then RED
            float rcb[4]; int iib[4];
            float4 hv[4], wv[4];
#pragma unroll
            for (int k = 0; k < 4; k++) {
                int e = ew0 + 4 + k;
                rcb[k] = Rcb[e];
                int jj = JJb[e];
                iib[k] = IIb[e];
                hv[k] = ((const float4*)(g_h + (size_t)jj * 128))[lane];
                wv[k] = *(const float4*)(sW + e * 132 + 4 * lane);
            }
#pragma unroll
            for (int k = 0; k < 4; k++) {
                red4(g_agg + (size_t)iib[k] * 128 + 4 * lane,
                     make_float4((wv[k].x + bf2v.x) * rcb[k] * hv[k].x,
                                 (wv[k].y + bf2v.y) * rcb[k] * hv[k].y,
                                 (wv[k].z + bf2v.z) * rcb[k] * hv[k].z,
                                 (wv[k].w + bf2v.w) * rcb[k] * hv[k].w));
            }
        }
    }
}

// ---------- k_out: out = ssp(agg@Wo1+bo1)@Wo2+bo2 (tf32 mma) ----------
__global__ void __launch_bounds__(512) k_out(const float* __restrict__ Wo1,
                                             const float* __restrict__ bo1,
                                             const float* __restrict__ Wo2,
                                             const float* __restrict__ bo2,
                                             float* __restrict__ out, int nRows) {
    extern __shared__ float sm[];
    int t = threadIdx.x;
    int w = t >> 5, lane = t & 31;
    int lq = lane >> 2, lr = lane & 3;
    int fgrp = w & 7, ahalf = w >> 3;
    int fA = fgrp * 16 + lq;

    int p2_lo = (2 * fgrp) * S_STRIDE + 2 * (lq & 3) + (lq >> 2);
    int p2_hi = p2_lo + S_STRIDE;

    float bo1_lo = __ldg(bo1 + fA), bo1_hi = __ldg(bo1 + fA + 8);
    float bo2_lo = __ldg(bo2 + fA), bo2_hi = __ldg(bo2 + fA + 8);

    const float2* bbase = (const float2*)sm + lane;

    int nTiles = (nRows + 127) >> 7;
    for (int tile = blockIdx.x; tile < nTiles; tile += gridDim.x) {
        int r0 = tile << 7;
        __syncthreads();
        for (int idx = t; idx < 4096; idx += 512) {
            int atom = idx >> 5, kq = idx & 31;
            int row = r0 + atom;
            float4 v = (row < nRows) ? ((const float4*)(g_agg + (size_t)row * 128))[kq]
                                     : make_float4(0.f, 0.f, 0.f, 0.f);
            int base = (atom >> 3) * NT_STRIDE + (kq >> 1) * S_STRIDE + 8 * (atom & 7) + (kq & 1);
            sm[base + 0] = __uint_as_float(tf32c(v.x));
            sm[base + 2] = __uint_as_float(tf32c(v.y));
            sm[base + 4] = __uint_as_float(tf32c(v.z));
            sm[base + 6] = __uint_as_float(tf32c(v.w));
        }
        uint32_t af[16][4];
#pragma unroll
        for (int s = 0; s < 16; s++) {
            af[s][0] = tf32c(__ldg(Wo1 + (8 * s + lr) * 128 + fA));
            af[s][1] = tf32c(__ldg(Wo1 + (8 * s + lr) * 128 + fA + 8));
            af[s][2] = tf32c(__ldg(Wo1 + (8 * s + 4 + lr) * 128 + fA));
            af[s][3] = tf32c(__ldg(Wo1 + (8 * s + 4 + lr) * 128 + fA + 8));
        }
        __syncthreads();
        float acc[8][4];
#pragma unroll
        for (int nt = 0; nt < 8; nt++) {
            acc[nt][0] = bo1_lo; acc[nt][1] = bo1_lo;
            acc[nt][2] = bo1_hi; acc[nt][3] = bo1_hi;
        }
#pragma unroll
        for (int nt = 0; nt < 8; nt++) {
            int gnt = ahalf * 8 + nt;
            const float2* bp = bbase + gnt * (NT_STRIDE / 2);
#pragma unroll
            for (int s = 0; s < 16; s++) {
                float2 bb = bp[s * (S_STRIDE / 2)];
                mma_tf32(acc[nt], af[s], __float_as_uint(bb.x), __float_as_uint(bb.y));
            }
        }
        __syncthreads();
#pragma unroll
        for (int nt = 0; nt < 8; nt++) {
            int gnt = ahalf * 8 + nt;
            float* base = sm + gnt * NT_STRIDE;
            int e0 = 2 * lr;
            base[p2_lo + e0 * 8]       = __uint_as_float(tf32c(sspf(acc[nt][0])));
            base[p2_lo + (e0 + 1) * 8] = __uint_as_float(tf32c(sspf(acc[nt][1])));
            base[p2_hi + e0 * 8]       = __uint_as_float(tf32c(sspf(acc[nt][2])));
            base[p2_hi + (e0 + 1) * 8] = __uint_as_float(tf32c(sspf(acc[nt][3])));
        }
#pragma unroll
        for (int s = 0; s < 16; s++) {
            af[s][0] = tf32c(__ldg(Wo2 + (8 * s + lr) * 128 + fA));
            af[s][1] = tf32c(__ldg(Wo2 + (8 * s + lr) * 128 + fA + 8));
            af[s][2] = tf32c(__ldg(Wo2 + (8 * s + 4 + lr) * 128 + fA));
            af[s][3] = tf32c(__ldg(Wo2 + (8 * s + 4 + lr) * 128 + fA + 8));
        }
        __syncthreads();
#pragma unroll
        for (int nt = 0; nt < 8; nt++) {
            acc[nt][0] = bo2_lo; acc[nt][1] = bo2_lo;
            acc[nt][2] = bo2_hi; acc[nt][3] = bo2_hi;
        }
#pragma unroll
        for (int nt = 0; nt < 8; nt++) {
            int gnt = ahalf * 8 + nt;
            const float2* bp = bbase + gnt * (NT_STRIDE / 2);
#pragma unroll
            for (int s = 0; s < 16; s++) {
                float2 bb = bp[s * (S_STRIDE / 2)];
                mma_tf32(acc[nt], af[s], __float_as_uint(bb.x), __float_as_uint(bb.y));
            }
        }
#pragma unroll
        for (int nt = 0; nt < 8; nt++) {
            int gnt = ahalf * 8 + nt;
            int row0 = r0 + gnt * 8 + 2 * lr;
            if (row0 < nRows) {
                out[(size_t)row0 * 128 + fA] = acc[nt][0];
                out[(size_t)row0 * 128 + fA + 8] = acc[nt][2];
            }
            if (row0 + 1 < nRows) {
                out[(size_t)(row0 + 1) * 128 + fA] = acc[nt][1];
                out[(size_t)(row0 + 1) * 128 + fA + 8] = acc[nt][3];
            }
        }
    }
}

// ---------- launch ----------
extern "C" void kernel_launch(void* const* d_in, const int* in_sizes, int n_in,
                              void* d_out, int out_size) {
    const float* x    = (const float*)d_in[0];
    const float* f_ij = (const float*)d_in[1];
    const float* rcut = (const float*)d_in[2];
    const float* W_in = (const float*)d_in[3];
    const float* b_in = (const float*)d_in[4];
    const float* Wf1  = (const float*)d_in[5];
    const float* bf1  = (const float*)d_in[6];
    const float* Wf2  = (const float*)d_in[7];
    const float* bf2  = (const float*)d_in[8];
    const float* Wo1  = (const float*)d_in[9];
    const float* bo1  = (const float*)d_in[10];
    const float* Wo2  = (const float*)d_in[11];
    const float* bo2  = (const float*)d_in[12];
    const int* idx_i  = (const int*)d_in[13];
    const int* idx_j  = (const int*)d_in[14];
    float* out = (float*)d_out;

    int nAtoms = in_sizes[0] / 128;
    int nPairs = in_sizes[2];

    const int SMEM_INOUT = SH_OUT * 4;       // 73728
    const int SMEM_EDGE  = EW_TOTAL * 4;     // 62976

    cudaFuncSetAttribute(k_in, cudaFuncAttributeMaxDynamicSharedMemorySize, SMEM_INOUT);
    cudaFuncSetAttribute(k_edge, cudaFuncAttributeMaxDynamicSharedMemorySize, SMEM_EDGE);
    cudaFuncSetAttribute(k_out, cudaFuncAttributeMaxDynamicSharedMemorySize, SMEM_INOUT);

    int rowTiles = (nAtoms + 127) / 128;
    k_in<<<rowTiles, 512, SMEM_INOUT>>>(x, W_in, b_in, nAtoms);
    k_edge<<<296, 256, SMEM_EDGE>>>(f_ij, rcut, idx_i, idx_j, Wf1, bf1, Wf2, bf2, nPairs);
    k_out<<<rowTiles, 512, SMEM_INOUT>>>(Wo1, bo1, Wo2, bo2, out, nAtoms);
}